// round 1
// baseline (speedup 1.0000x reference)
#include <cuda_runtime.h>

// ---------------- problem constants ----------------
#define IN_DIM 256            // S*F
#define KTOT   33152          // FEAT = IN_DIM + TRI
#define NTOT   8192           // NHEAD * S * D_MODEL
#define BATCH  8
#define S_DIM  32
#define OUT_F  64

// ---------------- gemm tiling ----------------
#define KTILE  1024           // smem feats tile per block (32 KB)
#define TCOLS  8              // columns per warp
#define WARPS  4              // warps per block
#define COLS_PER_BLOCK (WARPS * TCOLS)   // 32
#define GEMM_BLOCKS (NTOT / COLS_PER_BLOCK) // 256

// scratch (allocation-free rule: device globals)
__device__ float g_feats[BATCH * KTOT];  // [b][f]  (~1.06 MB)
__device__ float g_head [BATCH * NTOT];  // [b][n]  (256 KB)

using u64 = unsigned long long;

union F4U { float4 f4; u64 u[2]; float f[4]; };
union F2U { u64 u; float f[2]; };

// packed fp32x2 FMA (sm_100+/sm_103a; 2x FFMA throughput vs scalar FFMA)
__device__ __forceinline__ u64 ffma2(u64 a, u64 b, u64 c) {
    u64 d;
    asm("fma.rn.f32x2 %0, %1, %2, %3;" : "=l"(d) : "l"(a), "l"(b), "l"(c));
    return d;
}

// ---------------------------------------------------------------
// Kernel 1: build features  g_feats[b][f]
//   f < 256          : x_flat[b][f]
//   f >= 256, t=f-256: x[b][i]*x[b][j], (i,j) = t-th upper-tri pair
// ---------------------------------------------------------------
__global__ void feat_kernel(const float* __restrict__ x) {
    int f = blockIdx.x * blockDim.x + threadIdx.x;
    int b = blockIdx.y;
    if (f >= KTOT) return;
    const float* xb = x + b * IN_DIM;
    float v;
    if (f < IN_DIM) {
        v = xb[f];
    } else {
        int t = f - IN_DIM;
        // row i of upper triangle: off(i) = 256*i - i*(i-1)/2
        double disc = 513.0 * 513.0 - 8.0 * (double)t;
        int i = (int)((513.0 - sqrt(disc)) * 0.5);
        if (i < 0) i = 0;
        if (i > 255) i = 255;
        while (i < 255 && (256 * (i + 1) - ((i + 1) * i) / 2) <= t) i++;
        while (i > 0   && (256 * i - (i * (i - 1)) / 2) > t) i--;
        int off = 256 * i - (i * (i - 1)) / 2;
        int j = i + (t - off);
        v = xb[i] * xb[j];
    }
    g_feats[b * KTOT + f] = v;
}

// ---------------------------------------------------------------
// Kernel 2: head_out[b][n] = sum_f feats[b][f] * W[n][f] + bh[n]
//   Skinny GEMM, HBM-bound on W (1.086 GB, streamed once).
//   Warp owns 8 columns; feats chunk lives in registers (reused x8);
//   feats tile staged in smem [b][f]-planar (conflict-free LDS.128);
//   accumulation via packed f32x2 FMA over (f, f+1) pairs.
// ---------------------------------------------------------------
__global__ void __launch_bounds__(WARPS * 32, 2)
gemm_kernel(const float* __restrict__ W, const float* __restrict__ bh) {
    __shared__ __align__(16) float sfe[BATCH * KTILE];   // 32 KB

    const int warp = threadIdx.x >> 5;
    const int lane = threadIdx.x & 31;
    const int n0 = blockIdx.x * COLS_PER_BLOCK + warp * TCOLS;

    const float4* wrow[TCOLS];
#pragma unroll
    for (int t = 0; t < TCOLS; t++)
        wrow[t] = (const float4*)(W + (size_t)(n0 + t) * KTOT);

    u64 acc[TCOLS][BATCH];
#pragma unroll
    for (int t = 0; t < TCOLS; t++)
#pragma unroll
        for (int b = 0; b < BATCH; b++) acc[t][b] = 0ull;

    for (int k0 = 0; k0 < KTOT; k0 += KTILE) {
        const int kt = min(KTILE, KTOT - k0);   // 1024, tail 384 (both %128==0)
        __syncthreads();
        // stage feats tile: sfe[b][0..kt) = g_feats[b][k0..k0+kt)
        {
            const int nv = kt >> 2;             // float4 per plane
            for (int idx = threadIdx.x; idx < BATCH * nv; idx += blockDim.x) {
                int b = idx / nv;
                int r = idx - b * nv;
                ((float4*)(sfe + b * KTILE))[r] =
                    ((const float4*)(g_feats + (size_t)b * KTOT + k0))[r];
            }
        }
        __syncthreads();

        for (int kc = 0; kc < kt; kc += 128) {
            const int fo = kc + lane * 4;       // this lane's 4 f positions
            F4U fe[BATCH];
#pragma unroll
            for (int b = 0; b < BATCH; b++)
                fe[b].f4 = *((const float4*)(sfe + b * KTILE + fo));

            const int widx = ((k0 + kc) >> 2) + lane;
#pragma unroll
            for (int t = 0; t < TCOLS; t++) {
                F4U w; w.f4 = __ldg(&wrow[t][widx]);
#pragma unroll
                for (int b = 0; b < BATCH; b++) {
                    acc[t][b] = ffma2(fe[b].u[0], w.u[0], acc[t][b]);
                    acc[t][b] = ffma2(fe[b].u[1], w.u[1], acc[t][b]);
                }
            }
        }
    }

    // lane reduction + bias + store
#pragma unroll
    for (int t = 0; t < TCOLS; t++) {
        const int n = n0 + t;
        const float bias = bh[n];
#pragma unroll
        for (int b = 0; b < BATCH; b++) {
            F2U a; a.u = acc[t][b];
            float s = a.f[0] + a.f[1];
#pragma unroll
            for (int off = 16; off; off >>= 1)
                s += __shfl_xor_sync(0xffffffffu, s, off);
            if (lane == 0)
                g_head[b * NTOT + n] = s + bias;
        }
    }
}

// ---------------------------------------------------------------
// Kernel 3: out[b][s][of] = b_out[of]
//   + sum_{h,d} g_head[b][h*2048 + s*64 + d] * W_out[of][h*64 + d]
// one block per (b,s), 64 threads (one per of)
// ---------------------------------------------------------------
__global__ void out_kernel(const float* __restrict__ Wout,
                           const float* __restrict__ bout,
                           float* __restrict__ out) {
    const int bs = blockIdx.x;          // b*32 + s
    const int b = bs >> 5, s = bs & 31;
    __shared__ __align__(16) float row[256];
    const int tid = threadIdx.x;        // of

    for (int c = tid; c < 256; c += 64) {
        int h = c >> 6, d = c & 63;
        row[c] = g_head[b * NTOT + h * (S_DIM * 64) + s * 64 + d];
    }
    __syncthreads();

    float acc = bout[tid];
    const float4* wr = (const float4*)(Wout + tid * 256);
    const float4* rr = (const float4*)row;
#pragma unroll
    for (int q = 0; q < 64; q++) {
        float4 w = wr[q];
        float4 r = rr[q];
        acc += w.x * r.x + w.y * r.y + w.z * r.z + w.w * r.w;
    }
    out[bs * 64 + tid] = acc;
}

// ---------------------------------------------------------------
extern "C" void kernel_launch(void* const* d_in, const int* in_sizes, int n_in,
                              void* d_out, int out_size) {
    const float* input   = (const float*)d_in[0];  // [8,32,8]
    const float* W_heads = (const float*)d_in[1];  // [4,2048,33152]
    const float* b_heads = (const float*)d_in[2];  // [4,2048]
    const float* W_out   = (const float*)d_in[3];  // [64,256]
    const float* b_out   = (const float*)d_in[4];  // [64]
    float* out = (float*)d_out;                    // [8,32,64]

    dim3 g1((KTOT + 255) / 256, BATCH);
    feat_kernel<<<g1, 256>>>(input);
    gemm_kernel<<<GEMM_BLOCKS, WARPS * 32>>>(W_heads, b_heads);
    out_kernel<<<BATCH * S_DIM, OUT_F>>>(W_out, b_out, out);
}

// round 2
// speedup vs baseline: 1.6199x; 1.6199x over previous
#include <cuda_runtime.h>

// ---------------- problem constants ----------------
#define IN_DIM 256            // S*F
#define KTOT   33152          // FEAT = IN_DIM + TRI   (33152 % 128 == 0)
#define KVEC   (KTOT / 4)     // float4 per W row = 8288
#define NTOT   8192           // NHEAD * S * D_MODEL
#define BATCH  8
#define S_DIM  32
#define OUT_F  64

// ---------------- gemm tiling ----------------
#define KTILE  1024                      // smem feats tile (32 KB)
#define TCOLS  4                         // columns per warp
#define WARPS  8                         // warps per block
#define COLS_PER_BLOCK (WARPS * TCOLS)   // 32
#define GEMM_BLOCKS (NTOT / COLS_PER_BLOCK) // 256

// scratch (allocation-free rule: device globals)
__device__ float g_feats[BATCH * KTOT];  // [b][f]  (~1.06 MB, L2-resident)
__device__ float g_head [BATCH * NTOT];  // [b][n]  (256 KB)

using u64 = unsigned long long;

union F4U { float4 f4; u64 u[2]; float f[4]; };
union F2U { u64 u; float f[2]; };

// packed fp32x2 FMA (sm_103a: 2x FFMA throughput vs scalar 3-reg FFMA)
__device__ __forceinline__ u64 ffma2(u64 a, u64 b, u64 c) {
    u64 d;
    asm("fma.rn.f32x2 %0, %1, %2, %3;" : "=l"(d) : "l"(a), "l"(b), "l"(c));
    return d;
}

// ---------------------------------------------------------------
// Kernel 1: build features  g_feats[b][f]
//   block = (triu row i, batch b); thread j writes x[i]*x[j] for j>=i.
//   Row i=0's block also writes the linear part. No sqrt, no loops.
// ---------------------------------------------------------------
__global__ void feat_kernel(const float* __restrict__ x) {
    const int i = blockIdx.x;          // 0..255
    const int b = blockIdx.y;          // 0..7
    const int j = threadIdx.x;         // 0..255
    __shared__ float sx[IN_DIM];
    sx[j] = x[b * IN_DIM + j];
    __syncthreads();
    float* gb = g_feats + (size_t)b * KTOT;
    if (i == 0) gb[j] = sx[j];                       // linear features
    if (j >= i) {
        int off = 256 * i - (i * (i - 1)) / 2;       // triu row offset
        gb[IN_DIM + off + (j - i)] = sx[i] * sx[j];  // coalesced in j
    }
}

// ---------------------------------------------------------------
// Kernel 2: head_out[b][n] = sum_f feats[b][f] * W[n][f] + bh[n]
//   HBM-bound streaming GEMM over W (1.086 GB read once).
//   - warp owns 4 columns; 8 warps/block; 2 blocks/SM -> 16 warps/SM
//   - W double-buffered in registers (4 LDG.128 in flight per warp)
//   - feats tile staged in smem, [b]-planar, conflict-free LDS.128
//   - packed f32x2 FMA over (f, f+1) pairs
// ---------------------------------------------------------------
__global__ void __launch_bounds__(WARPS * 32, 2)
gemm_kernel(const float* __restrict__ W, const float* __restrict__ bh) {
    __shared__ __align__(16) float sfe[BATCH * KTILE];   // 32 KB

    const int warp = threadIdx.x >> 5;
    const int lane = threadIdx.x & 31;
    const int n0 = blockIdx.x * COLS_PER_BLOCK + warp * TCOLS;

    const float4* __restrict__ w4 = (const float4*)W;
    unsigned rowoff[TCOLS];
#pragma unroll
    for (int t = 0; t < TCOLS; t++)
        rowoff[t] = (unsigned)(n0 + t) * KVEC;

    u64 acc[TCOLS][BATCH];
#pragma unroll
    for (int t = 0; t < TCOLS; t++)
#pragma unroll
        for (int b = 0; b < BATCH; b++) acc[t][b] = 0ull;

    // preload first W chunk (k = 0..127)
    F4U wcur[TCOLS], wnxt[TCOLS];
#pragma unroll
    for (int t = 0; t < TCOLS; t++)
        wcur[t].f4 = __ldcs(&w4[(size_t)rowoff[t] + lane]);

    for (int k0 = 0; k0 < KTOT; k0 += KTILE) {
        const int kt = min(KTILE, KTOT - k0);   // 1024, tail 384 (%128==0)
        __syncthreads();
        // stage feats tile: sfe[b][0..kt) = g_feats[b][k0..k0+kt)
        {
            const int nv = kt >> 2;             // float4 per batch plane
            for (int idx = threadIdx.x; idx < BATCH * nv; idx += blockDim.x) {
                int b = idx / nv;
                int r = idx - b * nv;
                ((float4*)(sfe + b * KTILE))[r] =
                    ((const float4*)(g_feats + (size_t)b * KTOT + k0))[r];
            }
        }
        __syncthreads();

        for (int kc = 0; kc < kt; kc += 128) {
            // prefetch next 128-float W chunk (clamped; last iter re-reads tail)
            int nk = k0 + kc + 128;
            nk = (nk >= KTOT) ? (KTOT - 128) : nk;
            const unsigned widx = (unsigned)(nk >> 2) + lane;
#pragma unroll
            for (int t = 0; t < TCOLS; t++)
                wnxt[t].f4 = __ldcs(&w4[(size_t)rowoff[t] + widx]);

            // compute on wcur while wnxt is in flight
            const float* fp = sfe + kc + lane * 4;
#pragma unroll
            for (int b = 0; b < BATCH; b++) {
                F4U fe; fe.f4 = *(const float4*)(fp + b * KTILE);
#pragma unroll
                for (int t = 0; t < TCOLS; t++) {
                    acc[t][b] = ffma2(fe.u[0], wcur[t].u[0], acc[t][b]);
                    acc[t][b] = ffma2(fe.u[1], wcur[t].u[1], acc[t][b]);
                }
            }
#pragma unroll
            for (int t = 0; t < TCOLS; t++) wcur[t] = wnxt[t];
        }
    }

    // lane reduction + bias + store
#pragma unroll
    for (int t = 0; t < TCOLS; t++) {
        const int n = n0 + t;
        const float bias = bh[n];
#pragma unroll
        for (int b = 0; b < BATCH; b++) {
            F2U a; a.u = acc[t][b];
            float s = a.f[0] + a.f[1];
#pragma unroll
            for (int off = 16; off; off >>= 1)
                s += __shfl_xor_sync(0xffffffffu, s, off);
            if (lane == 0)
                g_head[b * NTOT + n] = s + bias;
        }
    }
}

// ---------------------------------------------------------------
// Kernel 3: out[b][s][of] = b_out[of]
//   + sum_{h,d} g_head[b][h*2048 + s*64 + d] * W_out[of][h*64 + d]
// one block per (b,s), 64 threads (one per of)
// ---------------------------------------------------------------
__global__ void out_kernel(const float* __restrict__ Wout,
                           const float* __restrict__ bout,
                           float* __restrict__ out) {
    const int bs = blockIdx.x;          // b*32 + s
    const int b = bs >> 5, s = bs & 31;
    __shared__ __align__(16) float row[256];
    const int tid = threadIdx.x;        // of

    for (int c = tid; c < 256; c += 64) {
        int h = c >> 6, d = c & 63;
        row[c] = g_head[b * NTOT + h * (S_DIM * 64) + s * 64 + d];
    }
    __syncthreads();

    float acc = bout[tid];
    const float4* wr = (const float4*)(Wout + tid * 256);
    const float4* rr = (const float4*)row;
#pragma unroll
    for (int q = 0; q < 64; q++) {
        float4 w = wr[q];
        float4 r = rr[q];
        acc += w.x * r.x + w.y * r.y + w.z * r.z + w.w * r.w;
    }
    out[bs * 64 + tid] = acc;
}

// ---------------------------------------------------------------
extern "C" void kernel_launch(void* const* d_in, const int* in_sizes, int n_in,
                              void* d_out, int out_size) {
    const float* input   = (const float*)d_in[0];  // [8,32,8]
    const float* W_heads = (const float*)d_in[1];  // [4,2048,33152]
    const float* b_heads = (const float*)d_in[2];  // [4,2048]
    const float* W_out   = (const float*)d_in[3];  // [64,256]
    const float* b_out   = (const float*)d_in[4];  // [64]
    float* out = (float*)d_out;                    // [8,32,64]

    dim3 g1(IN_DIM, BATCH);
    feat_kernel<<<g1, IN_DIM>>>(input);
    gemm_kernel<<<GEMM_BLOCKS, WARPS * 32>>>(W_heads, b_heads);
    out_kernel<<<BATCH * S_DIM, OUT_F>>>(W_out, b_out, out);
}